// round 2
// baseline (speedup 1.0000x reference)
#include <cuda_runtime.h>

#define T_DIM   2000
#define KFR     400
#define KD      400
#define A_DIM   100
#define TSPLIT  5
#define TCHUNK  (T_DIM / TSPLIT)
#define EPSF    1e-24f

// Deterministic partial buffers — fully overwritten every launch, no zeroing,
// no atomics. 800KB + 8KB scratch as __device__ globals (no allocations).
__device__ float d_gpart[TSPLIT * KFR * A_DIM];   // [split][k][a]
__device__ float d_llpart[TSPLIT * KFR];          // [split][k]

// One block per (split, k). Each warp processes 4 consecutive t-rows per batch:
// partial dots for the 4 rows are reduced with a packed butterfly (9 shfl / 4 rows)
// leaving row-sums in disjoint 8-lane groups, so exp/log/div run once per group
// (one MUFU warp-op serves 4 rows). X_fr is read exactly once (320 MB).
__global__ __launch_bounds__(128) void mmdglm_main(
    const float* __restrict__ tg, const int* __restrict__ mask,
    const float* __restrict__ X, const float* __restrict__ theta,
    int split_base)
{
    const int k     = blockIdx.y;
    const int split = blockIdx.x + split_base;
    const int warp  = threadIdx.x >> 5;
    const int lane  = threadIdx.x & 31;
    const float dt  = tg[1] - tg[0];
    const unsigned FULL = 0xffffffffu;

    float4 th = make_float4(0.f, 0.f, 0.f, 0.f);
    if (lane < 25) th = __ldg(((const float4*)theta) + lane);

    // After the packed reduction, lane's value holds row: 2*bit3 + bit4
    // lanes 0-7 -> row0, 8-15 -> row2, 16-23 -> row1, 24-31 -> row3
    const int myrow = (((lane >> 3) & 1) << 1) | ((lane >> 4) & 1);

    float g0 = 0.f, g1 = 0.f, g2 = 0.f, g3 = 0.f, llacc = 0.f;

    const int tbase = split * TCHUNK + warp * 4;
    const size_t RS = (size_t)KFR * A_DIM;   // row stride in floats for t+1

    #pragma unroll 2
    for (int b = 0; b < TCHUNK / 16; b++) {
        const int t0 = tbase + b * 16;
        const float* rowp = X + ((size_t)t0 * KFR + k) * A_DIM;

        float4 z = make_float4(0.f, 0.f, 0.f, 0.f);
        float4 x0 = z, x1 = z, x2 = z, x3 = z;
        if (lane < 25) {
            x0 = __ldg((const float4*)(rowp)          + lane);
            x1 = __ldg((const float4*)(rowp + RS)     + lane);
            x2 = __ldg((const float4*)(rowp + 2 * RS) + lane);
            x3 = __ldg((const float4*)(rowp + 3 * RS) + lane);
        }
        const int m = __ldg(mask + (size_t)(t0 + myrow) * KFR + k);

        float p0 = x0.x * th.x + x0.y * th.y + x0.z * th.z + x0.w * th.w;
        float p1 = x1.x * th.x + x1.y * th.y + x1.z * th.z + x1.w * th.w;
        float p2 = x2.x * th.x + x2.y * th.y + x2.z * th.z + x2.w * th.w;
        float p3 = x3.x * th.x + x3.y * th.y + x3.z * th.z + x3.w * th.w;

        // Packed butterfly: 9 shfl reduce 4 rows.
        float u0 = __shfl_xor_sync(FULL, p0, 16);
        float u1 = __shfl_xor_sync(FULL, p1, 16);
        float w01 = (lane & 16) ? (p1 + u1) : (p0 + u0);
        float u2 = __shfl_xor_sync(FULL, p2, 16);
        float u3 = __shfl_xor_sync(FULL, p3, 16);
        float w23 = (lane & 16) ? (p3 + u3) : (p2 + u2);
        float v01 = __shfl_xor_sync(FULL, w01, 8);
        float v23 = __shfl_xor_sync(FULL, w23, 8);
        float v = (lane & 8) ? (w23 + v23) : (w01 + v01);
        v += __shfl_xor_sync(FULL, v, 4);
        v += __shfl_xor_sync(FULL, v, 2);
        v += __shfl_xor_sync(FULL, v, 1);
        // v = full dot of row (t0 + myrow)

        const float r   = __expf(v);            // non_linearity = exp
        const float dtr = dt * r;
        float w, llc;
        if (m) {
            const float E = __expf(dtr);
            w   = __fdividef(dtr, E - 1.0f - EPSF);
            llc = __logf(1.0f - __expf(-dtr) + EPSF);
        } else {
            w   = -dtr;
            llc = -dtr;
        }
        llacc += llc;                            // 8x redundant; fixed at epilogue

        const float w0 = __shfl_sync(FULL, w, 0);
        const float w1 = __shfl_sync(FULL, w, 16);
        const float w2 = __shfl_sync(FULL, w, 8);
        const float w3 = __shfl_sync(FULL, w, 24);

        g0 += w0 * x0.x + w1 * x1.x + w2 * x2.x + w3 * x3.x;
        g1 += w0 * x0.y + w1 * x1.y + w2 * x2.y + w3 * x3.y;
        g2 += w0 * x0.z + w1 * x1.z + w2 * x2.z + w3 * x3.z;
        g3 += w0 * x0.w + w1 * x1.w + w2 * x2.w + w3 * x3.w;
    }

    // llacc: every lane in an 8-lane group holds the same row sums -> /8.
    #pragma unroll
    for (int o = 16; o; o >>= 1) llacc += __shfl_xor_sync(FULL, llacc, o);
    llacc *= 0.125f;

    __shared__ float sg[4][A_DIM];
    __shared__ float sll[4];
    if (lane < 25) *(float4*)&sg[warp][lane * 4] = make_float4(g0, g1, g2, g3);
    if (lane == 0) sll[warp] = llacc;
    __syncthreads();

    const int tid = threadIdx.x;
    if (tid < A_DIM) {
        const float s = sg[0][tid] + sg[1][tid] + sg[2][tid] + sg[3][tid];
        d_gpart[((size_t)split * KFR + k) * A_DIM + tid] = s;
    }
    if (tid == 0) d_llpart[split * KFR + k] = sll[0] + sll[1] + sll[2] + sll[3];
}

// Rank-1 gramians collapse everything to 6 scalars + two 100-vectors.
__global__ __launch_bounds__(128) void mmdglm_finalize(
    const float* __restrict__ phi_d, const float* __restrict__ phi_fr,
    float* __restrict__ out)
{
    __shared__ float shp[4][6];
    __shared__ float sc[6];
    const int tid = threadIdx.x, lane = tid & 31, warp = tid >> 5;
    const unsigned FULL = 0xffffffffu;

    float a0 = 0.f, a1 = 0.f, a2 = 0.f, a3 = 0.f, a4 = 0.f, a5 = 0.f;
    for (int i = tid; i < KFR; i += 128) {
        float l = 0.f;
        #pragma unroll
        for (int s = 0; s < TSPLIT; s++) l += d_llpart[s * KFR + i];
        const float pf = phi_fr[i], pd = phi_d[i];
        a0 += pf;      a1 += pf * pf;
        a2 += pd;      a3 += pd * pd;
        a4 += l * pf;  a5 += l * pf * pf;
    }
    #pragma unroll
    for (int o = 16; o; o >>= 1) {
        a0 += __shfl_xor_sync(FULL, a0, o);
        a1 += __shfl_xor_sync(FULL, a1, o);
        a2 += __shfl_xor_sync(FULL, a2, o);
        a3 += __shfl_xor_sync(FULL, a3, o);
        a4 += __shfl_xor_sync(FULL, a4, o);
        a5 += __shfl_xor_sync(FULL, a5, o);
    }
    if (lane == 0) {
        shp[warp][0] = a0; shp[warp][1] = a1; shp[warp][2] = a2;
        shp[warp][3] = a3; shp[warp][4] = a4; shp[warp][5] = a5;
    }
    __syncthreads();
    if (tid < 6) sc[tid] = shp[0][tid] + shp[1][tid] + shp[2][tid] + shp[3][tid];
    __syncthreads();

    const float S_fr = sc[0], Q_fr = sc[1], S_d = sc[2], Q_d = sc[3];
    const float P1 = sc[4], P2 = sc[5];
    const float n_fr = 0.5f * (float)KFR * (float)(KFR - 1);
    const float n_d  = 0.5f * (float)KD  * (float)(KD - 1);
    const float inv_kdkfr = 1.0f / ((float)KD * (float)KFR);

    if (tid == 0) {
        out[0] = (P1 * S_fr - P2) / n_fr - 2.0f * S_d * P1 * inv_kdkfr;
        out[1 + A_DIM] = (S_d * S_d - Q_d) / (2.0f * n_d)
                       + (S_fr * S_fr - Q_fr) / (2.0f * n_fr)
                       - 2.0f * S_d * S_fr * inv_kdkfr;
    }

    if (tid < A_DIM) {
        float Ga = 0.f, Ha = 0.f;
        for (int i = 0; i < KFR; i++) {
            const float pf = phi_fr[i];
            float g = 0.f;
            #pragma unroll
            for (int s = 0; s < TSPLIT; s++)
                g += d_gpart[((size_t)s * KFR + i) * A_DIM + tid];
            Ga += pf * g;
            Ha += pf * pf * g;
        }
        out[1 + tid] = (S_fr * Ga - Ha) / n_fr - 2.0f * S_d * Ga * inv_kdkfr;
    }
}

extern "C" void kernel_launch(void* const* d_in, const int* in_sizes, int n_in,
                              void* d_out, int out_size) {
    const float* t      = (const float*)d_in[0];
    const int*   mask   = (const int*)  d_in[1];
    const float* X      = (const float*)d_in[2];
    const float* theta  = (const float*)d_in[3];
    const float* phi_d  = (const float*)d_in[4];
    const float* phi_fr = (const float*)d_in[5];
    float* out = (float*)d_out;

    dim3 gA(3, KFR), gB(2, KFR);
    mmdglm_main<<<gA, 128>>>(t, mask, X, theta, 0);
    mmdglm_main<<<gB, 128>>>(t, mask, X, theta, 3);
    mmdglm_finalize<<<1, 128>>>(phi_d, phi_fr, out);
}

// round 3
// speedup vs baseline: 2.2988x; 2.2988x over previous
#include <cuda_runtime.h>

#define T_DIM   2000
#define KFR     400
#define KD      400
#define A_DIM   100
#define TSPLIT  5
#define TCHUNK  (T_DIM / TSPLIT)
#define NB      (TCHUNK / 16)          // 25 batches of 16 t-rows per block
#define EPSF    1e-24f

// Accumulators: [0..99]=Ga, [100..199]=Ha, [200]=P1, [201]=P2.
// Zeroed by mmdglm_zero each launch; atomically accumulated by main.
__device__ float d_acc[2 * A_DIM + 2];

__global__ void mmdglm_zero() {
    int i = threadIdx.x;
    if (i < 2 * A_DIM + 2) d_acc[i] = 0.0f;
}

// One block per (split, k). Each warp owns 4 consecutive t-rows per batch:
// packed butterfly (9 shfl / 4 rows) leaves row dot-products in disjoint
// 8-lane groups, so exp/log/div run once per group (1 MUFU op serves 4 rows).
// Double-buffered prefetch keeps 8 LDG.128 in flight. X_fr read once (320MB).
// Epilogue applies the phi_fr weighting and atomically folds into d_acc,
// so no large intermediate buffer and no serial finalize.
__global__ __launch_bounds__(128) void mmdglm_main(
    const float* __restrict__ tg, const int* __restrict__ mask,
    const float* __restrict__ X, const float* __restrict__ theta,
    const float* __restrict__ phi_fr)
{
    const int k     = blockIdx.y;
    const int split = blockIdx.x;
    const int warp  = threadIdx.x >> 5;
    const int lane  = threadIdx.x & 31;
    const float dt  = tg[1] - tg[0];
    const unsigned FULL = 0xffffffffu;

    float4 th = make_float4(0.f, 0.f, 0.f, 0.f);
    if (lane < 25) th = __ldg(((const float4*)theta) + lane);

    // lane's 8-lane group maps to row: lanes 0-7 -> r0, 8-15 -> r2,
    // 16-23 -> r1, 24-31 -> r3 (from the packed butterfly below)
    const int myrow = (((lane >> 3) & 1) << 1) | ((lane >> 4) & 1);

    float g0 = 0.f, g1 = 0.f, g2 = 0.f, g3 = 0.f, llacc = 0.f;

    const int tbase = split * TCHUNK + warp * 4;
    const size_t RS = (size_t)KFR * A_DIM;

    // prefetch batch 0
    float4 z = make_float4(0.f, 0.f, 0.f, 0.f);
    float4 c0 = z, c1 = z, c2 = z, c3 = z;
    {
        const float* rowp = X + ((size_t)tbase * KFR + k) * A_DIM;
        if (lane < 25) {
            c0 = __ldg((const float4*)(rowp)          + lane);
            c1 = __ldg((const float4*)(rowp + RS)     + lane);
            c2 = __ldg((const float4*)(rowp + 2 * RS) + lane);
            c3 = __ldg((const float4*)(rowp + 3 * RS) + lane);
        }
    }
    int mcur = __ldg(mask + (size_t)(tbase + myrow) * KFR + k);

    #pragma unroll 1
    for (int b = 0; b < NB; b++) {
        float4 n0 = z, n1 = z, n2 = z, n3 = z;
        int mnext = 0;
        if (b + 1 < NB) {
            const int tn = tbase + (b + 1) * 16;
            const float* rowp = X + ((size_t)tn * KFR + k) * A_DIM;
            if (lane < 25) {
                n0 = __ldg((const float4*)(rowp)          + lane);
                n1 = __ldg((const float4*)(rowp + RS)     + lane);
                n2 = __ldg((const float4*)(rowp + 2 * RS) + lane);
                n3 = __ldg((const float4*)(rowp + 3 * RS) + lane);
            }
            mnext = __ldg(mask + (size_t)(tn + myrow) * KFR + k);
        }

        float p0 = c0.x * th.x + c0.y * th.y + c0.z * th.z + c0.w * th.w;
        float p1 = c1.x * th.x + c1.y * th.y + c1.z * th.z + c1.w * th.w;
        float p2 = c2.x * th.x + c2.y * th.y + c2.z * th.z + c2.w * th.w;
        float p3 = c3.x * th.x + c3.y * th.y + c3.z * th.z + c3.w * th.w;

        // Packed butterfly: 9 shfl reduce all 4 rows.
        float u0 = __shfl_xor_sync(FULL, p0, 16);
        float u1 = __shfl_xor_sync(FULL, p1, 16);
        float w01 = (lane & 16) ? (p1 + u1) : (p0 + u0);
        float u2 = __shfl_xor_sync(FULL, p2, 16);
        float u3 = __shfl_xor_sync(FULL, p3, 16);
        float w23 = (lane & 16) ? (p3 + u3) : (p2 + u2);
        float v01 = __shfl_xor_sync(FULL, w01, 8);
        float v23 = __shfl_xor_sync(FULL, w23, 8);
        float v = (lane & 8) ? (w23 + v23) : (w01 + v01);
        v += __shfl_xor_sync(FULL, v, 4);
        v += __shfl_xor_sync(FULL, v, 2);
        v += __shfl_xor_sync(FULL, v, 1);
        // v = dot of row (t0 + myrow)

        const float r   = __expf(v);            // non_linearity = exp
        const float dtr = dt * r;
        float w, llc;
        if (mcur) {
            const float E = __expf(dtr);
            w   = __fdividef(dtr, E - 1.0f - EPSF);
            llc = __logf(1.0f - __expf(-dtr) + EPSF);
        } else {
            w   = -dtr;
            llc = -dtr;
        }
        llacc += llc;                            // 8x redundant; /8 at epilogue

        const float w0 = __shfl_sync(FULL, w, 0);
        const float w1 = __shfl_sync(FULL, w, 16);
        const float w2 = __shfl_sync(FULL, w, 8);
        const float w3 = __shfl_sync(FULL, w, 24);

        g0 += w0 * c0.x + w1 * c1.x + w2 * c2.x + w3 * c3.x;
        g1 += w0 * c0.y + w1 * c1.y + w2 * c2.y + w3 * c3.y;
        g2 += w0 * c0.z + w1 * c1.z + w2 * c2.z + w3 * c3.z;
        g3 += w0 * c0.w + w1 * c1.w + w2 * c2.w + w3 * c3.w;

        c0 = n0; c1 = n1; c2 = n2; c3 = n3; mcur = mnext;
    }

    #pragma unroll
    for (int o = 16; o; o >>= 1) llacc += __shfl_xor_sync(FULL, llacc, o);
    llacc *= 0.125f;

    __shared__ float sg[4][A_DIM];
    __shared__ float sll[4];
    if (lane < 25) *(float4*)&sg[warp][lane * 4] = make_float4(g0, g1, g2, g3);
    if (lane == 0) sll[warp] = llacc;
    __syncthreads();

    const float pf = __ldg(phi_fr + k);
    const int tid = threadIdx.x;
    if (tid < A_DIM) {
        const float s = sg[0][tid] + sg[1][tid] + sg[2][tid] + sg[3][tid];
        atomicAdd(&d_acc[tid],         pf * s);        // Ga
        atomicAdd(&d_acc[A_DIM + tid], pf * pf * s);   // Ha
    }
    if (tid == 0) {
        const float llb = sll[0] + sll[1] + sll[2] + sll[3];
        atomicAdd(&d_acc[2 * A_DIM],     pf * llb);        // P1
        atomicAdd(&d_acc[2 * A_DIM + 1], pf * pf * llb);   // P2
    }
}

// Rank-1 gramians: only phi moments + the accumulated Ga/Ha/P1/P2 remain.
__global__ __launch_bounds__(128) void mmdglm_finalize(
    const float* __restrict__ phi_d, const float* __restrict__ phi_fr,
    float* __restrict__ out)
{
    __shared__ float shp[4][4];
    __shared__ float sc[4];
    const int tid = threadIdx.x, lane = tid & 31, warp = tid >> 5;
    const unsigned FULL = 0xffffffffu;

    float a0 = 0.f, a1 = 0.f, a2 = 0.f, a3 = 0.f;
    for (int i = tid; i < KFR; i += 128) {
        const float pf = phi_fr[i], pd = phi_d[i];
        a0 += pf; a1 += pf * pf; a2 += pd; a3 += pd * pd;
    }
    #pragma unroll
    for (int o = 16; o; o >>= 1) {
        a0 += __shfl_xor_sync(FULL, a0, o);
        a1 += __shfl_xor_sync(FULL, a1, o);
        a2 += __shfl_xor_sync(FULL, a2, o);
        a3 += __shfl_xor_sync(FULL, a3, o);
    }
    if (lane == 0) { shp[warp][0] = a0; shp[warp][1] = a1;
                     shp[warp][2] = a2; shp[warp][3] = a3; }
    __syncthreads();
    if (tid < 4) sc[tid] = shp[0][tid] + shp[1][tid] + shp[2][tid] + shp[3][tid];
    __syncthreads();

    const float S_fr = sc[0], Q_fr = sc[1], S_d = sc[2], Q_d = sc[3];
    const float P1 = d_acc[2 * A_DIM], P2 = d_acc[2 * A_DIM + 1];
    const float n_fr = 0.5f * (float)KFR * (float)(KFR - 1);
    const float n_d  = 0.5f * (float)KD  * (float)(KD - 1);
    const float inv_kdkfr = 1.0f / ((float)KD * (float)KFR);

    if (tid == 0) {
        out[0] = (P1 * S_fr - P2) / n_fr - 2.0f * S_d * P1 * inv_kdkfr;
        out[1 + A_DIM] = (S_d * S_d - Q_d) / (2.0f * n_d)
                       + (S_fr * S_fr - Q_fr) / (2.0f * n_fr)
                       - 2.0f * S_d * S_fr * inv_kdkfr;
    }
    if (tid < A_DIM) {
        const float Ga = d_acc[tid], Ha = d_acc[A_DIM + tid];
        out[1 + tid] = (S_fr * Ga - Ha) / n_fr - 2.0f * S_d * Ga * inv_kdkfr;
    }
}

extern "C" void kernel_launch(void* const* d_in, const int* in_sizes, int n_in,
                              void* d_out, int out_size) {
    const float* t      = (const float*)d_in[0];
    const int*   mask   = (const int*)  d_in[1];
    const float* X      = (const float*)d_in[2];
    const float* theta  = (const float*)d_in[3];
    const float* phi_d  = (const float*)d_in[4];
    const float* phi_fr = (const float*)d_in[5];
    float* out = (float*)d_out;

    mmdglm_zero<<<1, 256>>>();
    dim3 grid(TSPLIT, KFR);
    mmdglm_main<<<grid, 128>>>(t, mask, X, theta, phi_fr);
    mmdglm_finalize<<<1, 128>>>(phi_d, phi_fr, out);
}